// round 8
// baseline (speedup 1.0000x reference)
#include <cuda_runtime.h>
#include <math.h>

// Problem constants
#define BATCH   2
#define NSEQ    2048
#define HEADS   8
#define DHEAD   64
#define DIMM    512
#define BHDIM   (BATCH*HEADS)        // 16
#define MROWS   (BATCH*NSEQ)         // 4096
#define QROWS   (BHDIM*NSEQ)         // 32768
#define TVALS   1025                 // 2*512+1
#define PLD     1028                 // padded row stride for P
#define RELTLD  1152                 // padded relT cols (9 tiles of 128)
#define SCALE_F 0.125f
#define QT_BH   (DHEAD*NSEQ)         // per-bh stride of [d][n] layout

typedef unsigned long long u64;

// ---------------- device scratch ---------------------------------------------
__device__ float g_Q [QROWS * DHEAD];                 // [bh][n][d] (scaled)
__device__ float g_Qt[BHDIM * DHEAD * NSEQ];          // [bh][d][n] (scaled)
__device__ float g_Kt[BHDIM * DHEAD * NSEQ];          // [bh][d][n]
__device__ float g_V [QROWS * DHEAD];                 // [bh][n][d]
__device__ float g_P [(size_t)QROWS * PLD];           // [bh*n][t] (pre-scaled)
__device__ float g_O [MROWS * DIMM];                  // [b*n][h*d]
__device__ float g_relT[DHEAD * RELTLD];              // [d][t] zero-padded

// ---------------- packed f32x2 primitives ------------------------------------
__device__ __forceinline__ u64 pack2(float lo, float hi) {
    u64 r; asm("mov.b64 %0, {%1, %2};" : "=l"(r) : "f"(lo), "f"(hi)); return r;
}
__device__ __forceinline__ u64 dup2(float v) {
    u64 r; asm("mov.b64 %0, {%1, %1};" : "=l"(r) : "f"(v)); return r;
}
__device__ __forceinline__ void unpack2(u64 v, float& lo, float& hi) {
    asm("mov.b64 {%0, %1}, %2;" : "=f"(lo), "=f"(hi) : "l"(v));
}
__device__ __forceinline__ void fma2(u64& d, u64 a, u64 b) {
    asm("fma.rn.f32x2 %0, %1, %2, %0;" : "+l"(d) : "l"(a), "l"(b));
}
__device__ __forceinline__ void mul2(u64& d, u64 a) {
    asm("mul.rn.f32x2 %0, %0, %1;" : "+l"(d) : "l"(a));
}

// ---------------- cp.async helpers --------------------------------------------
__device__ __forceinline__ void cp16(float* dst, const float* src) {
    unsigned s = (unsigned)__cvta_generic_to_shared(dst);
    asm volatile("cp.async.ca.shared.global [%0], [%1], 16;" :: "r"(s), "l"(src));
}
#define CP_COMMIT() asm volatile("cp.async.commit_group;")
#define CP_WAIT0()  asm volatile("cp.async.wait_group 0;")

// ---------------- micro tiles --------------------------------------------------
__device__ __forceinline__ void fma8x8(float4 a0, float4 a1,
                                       float4 b0, float4 b1, u64 (&c)[8][4]) {
    u64 p0 = pack2(b0.x, b0.y), p1 = pack2(b0.z, b0.w);
    u64 p2 = pack2(b1.x, b1.y), p3 = pack2(b1.z, b1.w);
    float as[8] = {a0.x, a0.y, a0.z, a0.w, a1.x, a1.y, a1.z, a1.w};
    #pragma unroll
    for (int ii = 0; ii < 8; ii++) {
        u64 ad = dup2(as[ii]);
        fma2(c[ii][0], ad, p0); fma2(c[ii][1], ad, p1);
        fma2(c[ii][2], ad, p2); fma2(c[ii][3], ad, p3);
    }
}
__device__ __forceinline__ void fma8x4(float4 a0, float4 a1, float4 b,
                                       u64 (&c)[8][2]) {
    u64 p0 = pack2(b.x, b.y), p1 = pack2(b.z, b.w);
    float as[8] = {a0.x, a0.y, a0.z, a0.w, a1.x, a1.y, a1.z, a1.w};
    #pragma unroll
    for (int ii = 0; ii < 8; ii++) {
        u64 ad = dup2(as[ii]);
        fma2(c[ii][0], ad, p0); fma2(c[ii][1], ad, p1);
    }
}
__device__ __forceinline__ void fma4x8(float4 a, float4 b0, float4 b1,
                                       u64 (&c)[4][4]) {
    u64 p0 = pack2(b0.x, b0.y), p1 = pack2(b0.z, b0.w);
    u64 p2 = pack2(b1.x, b1.y), p3 = pack2(b1.z, b1.w);
    float as[4] = {a.x, a.y, a.z, a.w};
    #pragma unroll
    for (int ii = 0; ii < 4; ii++) {
        u64 ad = dup2(as[ii]);
        fma2(c[ii][0], ad, p0); fma2(c[ii][1], ad, p1);
        fma2(c[ii][2], ad, p2); fma2(c[ii][3], ad, p3);
    }
}

__device__ __forceinline__ void unpack_acc8(const u64 (&acc)[8][4], float (&s)[8][8]) {
    #pragma unroll
    for (int ii = 0; ii < 8; ii++)
        #pragma unroll
        for (int p = 0; p < 4; p++)
            unpack2(acc[ii][p], s[ii][2*p], s[ii][2*p+1]);
}
__device__ __forceinline__ void unpack_acc4(const u64 (&acc)[4][4], float (&s)[4][8]) {
    #pragma unroll
    for (int ii = 0; ii < 4; ii++)
        #pragma unroll
        for (int p = 0; p < 4; p++)
            unpack2(acc[ii][p], s[ii][2*p], s[ii][2*p+1]);
}

// ---------------- 128x128 sgemm core (BK=16, 256 thr, 8x8/thread) ------------
__device__ __forceinline__ void sgemm128(
    const float* __restrict__ A, int lda,
    const float* __restrict__ B, int ldb,
    int kdim, u64 (&acc)[8][4],
    float (*Ats)[128], float (*Bs)[128])
{
    const int tid = threadIdx.x;
    const int ty  = tid >> 4, tx = tid & 15;
    const int ar  = tid >> 1;
    const int ak  = (tid & 1) << 3;
    const int br0 = tid >> 5;
    const int bc  = (tid & 31) << 2;

    float4 a0 = *(const float4*)(A + (size_t)ar * lda + ak);
    float4 a1 = *(const float4*)(A + (size_t)ar * lda + ak + 4);
    float4 b0 = *(const float4*)(B + (size_t)br0 * ldb + bc);
    float4 b1 = *(const float4*)(B + (size_t)(br0 + 8) * ldb + bc);

    for (int k0 = 0; k0 < kdim; k0 += 16) {
        Ats[ak + 0][ar] = a0.x; Ats[ak + 1][ar] = a0.y;
        Ats[ak + 2][ar] = a0.z; Ats[ak + 3][ar] = a0.w;
        Ats[ak + 4][ar] = a1.x; Ats[ak + 5][ar] = a1.y;
        Ats[ak + 6][ar] = a1.z; Ats[ak + 7][ar] = a1.w;
        *(float4*)(&Bs[br0][bc])     = b0;
        *(float4*)(&Bs[br0 + 8][bc]) = b1;
        __syncthreads();
        if (k0 + 16 < kdim) {
            a0 = *(const float4*)(A + (size_t)ar * lda + k0 + 16 + ak);
            a1 = *(const float4*)(A + (size_t)ar * lda + k0 + 16 + ak + 4);
            b0 = *(const float4*)(B + (size_t)(k0 + 16 + br0) * ldb + bc);
            b1 = *(const float4*)(B + (size_t)(k0 + 24 + br0) * ldb + bc);
        }
        #pragma unroll
        for (int kk = 0; kk < 16; kk++) {
            float4 av0 = *(const float4*)(&Ats[kk][ty << 3]);
            float4 av1 = *(const float4*)(&Ats[kk][(ty << 3) + 4]);
            float4 bv0 = *(const float4*)(&Bs[kk][tx << 3]);
            float4 bv1 = *(const float4*)(&Bs[kk][(tx << 3) + 4]);
            fma8x8(av0, av1, bv0, bv1, acc);
        }
        __syncthreads();
    }
}

// ---------------- 64x128 sgemm core (BK=16, 256 thr, 4x8/thread) -------------
__device__ __forceinline__ void sgemm64(
    const float* __restrict__ A, int lda,
    const float* __restrict__ B, int ldb,
    int kdim, u64 (&acc)[4][4],
    float (*Ats)[68], float (*Bs)[128])
{
    const int tid = threadIdx.x;
    const int ty  = tid >> 4, tx = tid & 15;
    const int ar  = tid >> 2;            // 0..63
    const int ak  = (tid & 3) << 2;      // 0,4,8,12
    const int br0 = tid >> 5;            // 0..7
    const int bc  = (tid & 31) << 2;     // 0..124

    float4 a  = *(const float4*)(A + (size_t)ar * lda + ak);
    float4 b0 = *(const float4*)(B + (size_t)br0 * ldb + bc);
    float4 b1 = *(const float4*)(B + (size_t)(br0 + 8) * ldb + bc);

    for (int k0 = 0; k0 < kdim; k0 += 16) {
        Ats[ak + 0][ar] = a.x; Ats[ak + 1][ar] = a.y;
        Ats[ak + 2][ar] = a.z; Ats[ak + 3][ar] = a.w;
        *(float4*)(&Bs[br0][bc])     = b0;
        *(float4*)(&Bs[br0 + 8][bc]) = b1;
        __syncthreads();
        if (k0 + 16 < kdim) {
            a  = *(const float4*)(A + (size_t)ar * lda + k0 + 16 + ak);
            b0 = *(const float4*)(B + (size_t)(k0 + 16 + br0) * ldb + bc);
            b1 = *(const float4*)(B + (size_t)(k0 + 24 + br0) * ldb + bc);
        }
        #pragma unroll
        for (int kk = 0; kk < 16; kk++) {
            float4 av  = *(const float4*)(&Ats[kk][ty << 2]);
            float4 bv0 = *(const float4*)(&Bs[kk][tx << 3]);
            float4 bv1 = *(const float4*)(&Bs[kk][(tx << 3) + 4]);
            fma4x8(av, bv0, bv1, acc);
        }
        __syncthreads();
    }
}

// ---------------- kernel 0: transpose+pad rel_emb ----------------------------
__global__ void __launch_bounds__(256) transpose_rel_kernel(
    const float* __restrict__ rel, float* __restrict__ relT)
{
    int idx = blockIdx.x * 256 + threadIdx.x;
    if (idx < DHEAD * RELTLD) {
        int d = idx / RELTLD;
        int t = idx % RELTLD;
        relT[idx] = (t < TVALS) ? rel[(size_t)t * DHEAD + d] : 0.0f;
    }
}

// ---------------- kernel 1: fused QKV projection (64x128 tiles) --------------
// grid (64, 12): y*128 in [0,512)=Q (scaled, 2 layouts), [512,1024)=Kt, rest V
__global__ void __launch_bounds__(256, 2) gemm_qkv_kernel(
    const float* __restrict__ x,
    const float* __restrict__ Wq, const float* __restrict__ Wkv,
    float* __restrict__ Q, float* __restrict__ Qt,
    float* __restrict__ Kt, float* __restrict__ V)
{
    __shared__ float Ats[16][68];
    __shared__ float Bs[16][128];

    const int m0 = blockIdx.x << 6;
    const int c0 = blockIdx.y << 7;

    const float* W; int wcol, ldw;
    if (c0 < 512) { W = Wq;  wcol = c0;       ldw = 512;  }
    else          { W = Wkv; wcol = c0 - 512; ldw = 1024; }

    u64 acc[4][4] = {};
    sgemm64(x + (size_t)m0 * DIMM, DIMM, W + wcol, ldw, DIMM, acc, Ats, Bs);

    float s[4][8];
    unpack_acc4(acc, s);

    const int ty = threadIdx.x >> 4, tx = threadIdx.x & 15;
    const int colb = c0 + (tx << 3);
    const int r0 = m0 + (ty << 2);        // 4 consecutive rows, same batch
    const int b = r0 >> 11, n4 = r0 & 2047;

    if (c0 < 512) {
        #pragma unroll
        for (int ii = 0; ii < 4; ii++)
            #pragma unroll
            for (int jj = 0; jj < 8; jj++) s[ii][jj] *= SCALE_F;
        int head = (colb & 511) >> 6, dl = colb & 63;
        #pragma unroll
        for (int ii = 0; ii < 4; ii++) {
            size_t base = (((size_t)(b * HEADS + head)) * NSEQ + n4 + ii) * DHEAD + dl;
            *(float4*)(Q + base)     = make_float4(s[ii][0], s[ii][1], s[ii][2], s[ii][3]);
            *(float4*)(Q + base + 4) = make_float4(s[ii][4], s[ii][5], s[ii][6], s[ii][7]);
        }
        #pragma unroll
        for (int jj = 0; jj < 8; jj++) {
            int col = colb + jj;
            int h2 = (col & 511) >> 6, d2 = col & 63;
            size_t base = (size_t)(b * HEADS + h2) * QT_BH + (size_t)d2 * NSEQ + n4;
            *(float4*)(Qt + base) = make_float4(s[0][jj], s[1][jj], s[2][jj], s[3][jj]);
        }
    } else if (c0 < 1024) {
        #pragma unroll
        for (int jj = 0; jj < 8; jj++) {
            int col = colb + jj;
            int h2 = (col & 511) >> 6, d2 = col & 63;
            size_t base = (size_t)(b * HEADS + h2) * QT_BH + (size_t)d2 * NSEQ + n4;
            *(float4*)(Kt + base) = make_float4(s[0][jj], s[1][jj], s[2][jj], s[3][jj]);
        }
    } else {
        int head = (colb & 511) >> 6, dl = colb & 63;
        #pragma unroll
        for (int ii = 0; ii < 4; ii++) {
            size_t base = (((size_t)(b * HEADS + head)) * NSEQ + n4 + ii) * DHEAD + dl;
            *(float4*)(V + base)     = make_float4(s[ii][0], s[ii][1], s[ii][2], s[ii][3]);
            *(float4*)(V + base + 4) = make_float4(s[ii][4], s[ii][5], s[ii][6], s[ii][7]);
        }
    }
}

// ---------------- kernel 2: P = Qscaled @ relT  (32768 x 1025 x 64) ----------
__global__ void __launch_bounds__(256, 2) gemm_p_kernel(
    const float* __restrict__ Q, const float* __restrict__ relT,
    float* __restrict__ P)
{
    __shared__ float Ats[16][128];
    __shared__ float Bs[16][128];

    const int m0 = blockIdx.x << 7;
    const int t0 = blockIdx.y << 7;

    u64 acc[8][4] = {};
    sgemm128(Q + (size_t)m0 * DHEAD, DHEAD, relT + t0, RELTLD, DHEAD, acc, Ats, Bs);

    float s[8][8];
    unpack_acc8(acc, s);

    const int ty = threadIdx.x >> 4, tx = threadIdx.x & 15;
    const int colb = t0 + (tx << 3);
    const bool full = (t0 + 127) < TVALS;

    #pragma unroll
    for (int ii = 0; ii < 8; ii++) {
        size_t base = (size_t)(m0 + (ty << 3) + ii) * PLD + colb;
        if (full) {
            *(float4*)(P + base)     = make_float4(s[ii][0], s[ii][1], s[ii][2], s[ii][3]);
            *(float4*)(P + base + 4) = make_float4(s[ii][4], s[ii][5], s[ii][6], s[ii][7]);
        } else {
            #pragma unroll
            for (int jj = 0; jj < 8; jj++)
                if (colb + jj < TVALS) P[base + jj] = s[ii][jj];
        }
    }
}

// ---------------- kernel 3: flash attention, Br=Bc=128, cp.async pipeline ----
// grid (16, 16), 256 threads, 224 KB dynamic smem, 1 CTA/SM.
__global__ void __launch_bounds__(256, 1) flash_kernel(
    const float* __restrict__ Qt, const float* __restrict__ Kt,
    const float* __restrict__ V, const float* __restrict__ P,
    float* __restrict__ O)
{
    extern __shared__ float smf[];
    float* Qts  = smf;                   // [64][128]
    float* Ktb0 = smf + 8192;            // [64][128] double-buffered
    float* Ktb1 = smf + 16384;
    float* Vb0  = smf + 24576;           // [128][64] double-buffered
    float* Vb1  = smf + 32768;
    float* Pts  = smf + 40960;           // [128][128] swizzled

    const int bh = blockIdx.y;
    const int n0 = blockIdx.x << 7;
    const float* Qb = Qt + (size_t)bh * QT_BH;
    const float* Kb = Kt + (size_t)bh * QT_BH;
    const float* Vg = V  + (size_t)bh * NSEQ * DHEAD;
    const float* Pb = P  + (size_t)bh * NSEQ * PLD;

    const int tid = threadIdx.x;
    const int ty  = tid >> 4, tx = tid & 15;
    const int kd  = tid >> 1;                 // unused placeholder removed
    (void)kd;

    // per-thread copy coords
    const int cd  = tid >> 5;                 // base d-row for K copies (step 8)
    const int cc  = (tid & 31) << 2;          // K col within tile
    const int vr  = tid >> 4;                 // base row for V copies (step 16)
    const int vc  = (tid & 15) << 2;          // V col

    // stage Q once (plain stores; visible after first barrier)
    #pragma unroll
    for (int q = 0; q < 8; q++) {
        int d = cd + (q << 3);
        *(float4*)(Qts + d * 128 + cc) =
            *(const float4*)(Qb + (size_t)d * NSEQ + n0 + cc);
    }

    // prologue: cp.async tile 0
    #pragma unroll
    for (int q = 0; q < 8; q++) {
        int d = cd + (q << 3);
        cp16(Ktb0 + d * 128 + cc, Kb + (size_t)d * NSEQ + cc);
    }
    #pragma unroll
    for (int q = 0; q < 8; q++) {
        int row = vr + (q << 4);
        cp16(Vb0 + row * 64 + vc, Vg + (size_t)row * DHEAD + vc);
    }
    CP_COMMIT();

    float m_i[8], l_i[8];
    u64 o2[8][2];
    #pragma unroll
    for (int ii = 0; ii < 8; ii++) {
        m_i[ii] = -1e30f; l_i[ii] = 0.0f;
        o2[ii][0] = 0ull; o2[ii][1] = 0ull;
    }

    int cur = 0;
    for (int jt = 0; jt < NSEQ / 128; jt++) {
        const int j0 = jt << 7;
        const float* Kc = cur ? Ktb1 : Ktb0;
        const float* Vc = cur ? Vb1  : Vb0;

        CP_WAIT0();
        __syncthreads();                                   // A: K/V cur ready, prev PV done

        // ---- S = Q K^T ------------------------------------------------------
        u64 s2[8][4] = {};
        #pragma unroll 4
        for (int d = 0; d < 64; d++) {
            float4 av0 = *(const float4*)(Qts + d * 128 + (ty << 3));
            float4 av1 = *(const float4*)(Qts + d * 128 + (ty << 3) + 4);
            float4 bv0 = *(const float4*)(Kc + d * 128 + (tx << 3));
            float4 bv1 = *(const float4*)(Kc + d * 128 + (tx << 3) + 4);
            fma8x8(av0, av1, bv0, bv1, s2);
        }

        // ---- bias + online softmax ------------------------------------------
        float s[8][8];
        unpack_acc8(s2, s);
        float rowmax[8];
        #pragma unroll
        for (int ii = 0; ii < 8; ii++) {
            int n = n0 + (ty << 3) + ii;
            const float* prow = Pb + (size_t)n * PLD;
            int basei = n - j0 + 512 - (tx << 3);
            rowmax[ii] = -1e30f;
            #pragma unroll
            for (int jj = 0; jj < 8; jj++) {
                int idx = basei - jj;
                idx = idx < 0 ? 0 : (idx > 1024 ? 1024 : idx);
                float v = s[ii][jj] + prow[idx];
                s[ii][jj] = v;
                rowmax[ii] = fmaxf(rowmax[ii], v);
            }
        }
        #pragma unroll
        for (int msk = 1; msk < 16; msk <<= 1)
            #pragma unroll
            for (int ii = 0; ii < 8; ii++)
                rowmax[ii] = fmaxf(rowmax[ii],
                                   __shfl_xor_sync(0xffffffffu, rowmax[ii], msk));

        float rs[8];
        #pragma unroll
        for (int ii = 0; ii < 8; ii++) {
            float mnew = fmaxf(m_i[ii], rowmax[ii]);
            float corr = __expf(m_i[ii] - mnew);
            m_i[ii] = mnew;
            rs[ii] = 0.0f;
            #pragma unroll
            for (int jj = 0; jj < 8; jj++) {
                float p = __expf(s[ii][jj] - mnew);
                s[ii][jj] = p;
                rs[ii] += p;
            }
            l_i[ii] *= corr;
            u64 c2 = dup2(corr);
            mul2(o2[ii][0], c2);
            mul2(o2[ii][1], c2);
        }
        #pragma unroll
        for (int msk = 1; msk < 16; msk <<= 1)
            #pragma unroll
            for (int ii = 0; ii < 8; ii++)
                rs[ii] += __shfl_xor_sync(0xffffffffu, rs[ii], msk);
        #pragma unroll
        for (int ii = 0; ii < 8; ii++) l_i[ii] += rs[ii];

        // ---- stage S transposed into Pts (swizzled col-quads) ---------------
        {
            int sw = (tx & 7) << 2;
            #pragma unroll
            for (int jj = 0; jj < 8; jj++) {
                int j = (tx << 3) + jj;
                int iq0 = ((ty << 1)       ^ sw) << 2;
                int iq1 = (((ty << 1) | 1) ^ sw) << 2;
                *(float4*)(Pts + j * 128 + iq0) =
                    make_float4(s[0][jj], s[1][jj], s[2][jj], s[3][jj]);
                *(float4*)(Pts + j * 128 + iq1) =
                    make_float4(s[4][jj], s[5][jj], s[6][jj], s[7][jj]);
            }
        }
        __syncthreads();                                   // B: Pts ready, QK done

        // ---- issue cp.async for next tile (overlaps PV) ----------------------
        if (jt + 1 < NSEQ / 128) {
            float* Kn = cur ? Ktb0 : Ktb1;
            float* Vn = cur ? Vb0  : Vb1;
            const int jn = j0 + 128;
            #pragma unroll
            for (int q = 0; q < 8; q++) {
                int d = cd + (q << 3);
                cp16(Kn + d * 128 + cc, Kb + (size_t)d * NSEQ + jn + cc);
            }
            #pragma unroll
            for (int q = 0; q < 8; q++) {
                int row = vr + (q << 4);
                cp16(Vn + row * 64 + vc, Vg + (size_t)(jn + row) * DHEAD + vc);
            }
            CP_COMMIT();
        }

        // ---- O += P V --------------------------------------------------------
        #pragma unroll 4
        for (int j = 0; j < 128; j++) {
            int sw = ((j >> 3) & 7) << 2;
            float4 av0 = *(const float4*)(Pts + j * 128 + ((((ty << 1))     ^ sw) << 2));
            float4 av1 = *(const float4*)(Pts + j * 128 + ((((ty << 1) | 1) ^ sw) << 2));
            float4 bv  = *(const float4*)(Vc + j * 64 + (tx << 2));
            fma8x4(av0, av1, bv, o2);
        }
        cur ^= 1;
    }

    // epilogue: normalize, write [b][n][h*64+dd]
    const int b = bh >> 3, head = bh & 7;
    #pragma unroll
    for (int ii = 0; ii < 8; ii++) {
        int n = n0 + (ty << 3) + ii;
        float inv = 1.0f / l_i[ii];
        size_t base = ((size_t)(b * NSEQ + n)) * DIMM + (head << 6) + (tx << 2);
        float4 v;
        unpack2(o2[ii][0], v.x, v.y);
        unpack2(o2[ii][1], v.z, v.w);
        v.x *= inv; v.y *= inv; v.z *= inv; v.w *= inv;
        *(float4*)(O + base) = v;
    }
}

// ---------------- kernel 4: output projection + bias (64x128 tiles) ----------
__global__ void __launch_bounds__(256, 2) gemm_out_kernel(
    const float* __restrict__ O, const float* __restrict__ Wo,
    const float* __restrict__ bo, float* __restrict__ out)
{
    __shared__ float Ats[16][68];
    __shared__ float Bs[16][128];

    const int m0 = blockIdx.x << 6;
    const int n0 = blockIdx.y << 7;

    u64 acc[4][4] = {};
    sgemm64(O + (size_t)m0 * DIMM, DIMM, Wo + n0, DIMM, DIMM, acc, Ats, Bs);

    float s[4][8];
    unpack_acc4(acc, s);

    const int ty = threadIdx.x >> 4, tx = threadIdx.x & 15;
    const int col = n0 + (tx << 3);
    float4 bias0 = *(const float4*)(bo + col);
    float4 bias1 = *(const float4*)(bo + col + 4);
    #pragma unroll
    for (int ii = 0; ii < 4; ii++) {
        size_t base = (size_t)(m0 + (ty << 2) + ii) * DIMM + col;
        *(float4*)(out + base)     = make_float4(s[ii][0] + bias0.x, s[ii][1] + bias0.y,
                                                 s[ii][2] + bias0.z, s[ii][3] + bias0.w);
        *(float4*)(out + base + 4) = make_float4(s[ii][4] + bias1.x, s[ii][5] + bias1.y,
                                                 s[ii][6] + bias1.z, s[ii][7] + bias1.w);
    }
}

// ---------------- launch -------------------------------------------------------
extern "C" void kernel_launch(void* const* d_in, const int* in_sizes, int n_in,
                              void* d_out, int out_size)
{
    const float* x    = (const float*)d_in[0];
    const float* Wq   = (const float*)d_in[1];
    const float* Wkv  = (const float*)d_in[2];
    const float* Wo   = (const float*)d_in[3];
    const float* bo   = (const float*)d_in[4];
    const float* rel  = (const float*)d_in[5];
    float* out = (float*)d_out;

    float *Qp, *Qtp, *Ktp, *Vp, *Pp, *Op, *rTp;
    cudaGetSymbolAddress((void**)&Qp,  g_Q);
    cudaGetSymbolAddress((void**)&Qtp, g_Qt);
    cudaGetSymbolAddress((void**)&Ktp, g_Kt);
    cudaGetSymbolAddress((void**)&Vp,  g_V);
    cudaGetSymbolAddress((void**)&Pp,  g_P);
    cudaGetSymbolAddress((void**)&Op,  g_O);
    cudaGetSymbolAddress((void**)&rTp, g_relT);

    cudaFuncSetAttribute(flash_kernel,
                         cudaFuncAttributeMaxDynamicSharedMemorySize, 229376);

    transpose_rel_kernel<<<(DHEAD * RELTLD + 255) / 256, 256>>>(rel, rTp);
    gemm_qkv_kernel<<<dim3(MROWS / 64, 12), 256>>>(x, Wq, Wkv, Qp, Qtp, Ktp, Vp);
    gemm_p_kernel<<<dim3(QROWS / 128, 9), 256>>>(Qp, rTp, Pp);
    flash_kernel<<<dim3(NSEQ / 128, BHDIM), 256, 229376>>>(Qtp, Ktp, Vp, Pp, Op);
    gemm_out_kernel<<<dim3(MROWS / 64, DIMM / 128), 256>>>(Op, Wo, bo, out);
}

// round 9
// speedup vs baseline: 1.1327x; 1.1327x over previous
#include <cuda_runtime.h>
#include <math.h>

// Problem constants
#define BATCH   2
#define NSEQ    2048
#define HEADS   8
#define DHEAD   64
#define DIMM    512
#define BHDIM   (BATCH*HEADS)        // 16
#define MROWS   (BATCH*NSEQ)         // 4096
#define QROWS   (BHDIM*NSEQ)         // 32768
#define TVALS   1025                 // 2*512+1
#define PLD     1028                 // padded row stride for P
#define RELTLD  1152                 // padded relT cols (9 tiles of 128)
#define SCALE_F 0.125f
#define QT_BH   (DHEAD*NSEQ)         // per-bh stride of [d][n] layout

typedef unsigned long long u64;

// ---------------- device scratch ---------------------------------------------
__device__ float g_Q [QROWS * DHEAD];                 // [bh][n][d] (scaled)
__device__ float g_Qt[BHDIM * DHEAD * NSEQ];          // [bh][d][n] (scaled)
__device__ float g_Kt[BHDIM * DHEAD * NSEQ];          // [bh][d][n]
__device__ float g_V [QROWS * DHEAD];                 // [bh][n][d]
__device__ float g_P [(size_t)QROWS * PLD];           // [bh*n][t] (pre-scaled)
__device__ float g_O [MROWS * DIMM];                  // [b*n][h*d]
__device__ float g_relT[DHEAD * RELTLD];              // [d][t] zero-padded

// ---------------- packed f32x2 primitives ------------------------------------
__device__ __forceinline__ u64 pack2(float lo, float hi) {
    u64 r; asm("mov.b64 %0, {%1, %2};" : "=l"(r) : "f"(lo), "f"(hi)); return r;
}
__device__ __forceinline__ u64 dup2(float v) {
    u64 r; asm("mov.b64 %0, {%1, %1};" : "=l"(r) : "f"(v)); return r;
}
__device__ __forceinline__ void unpack2(u64 v, float& lo, float& hi) {
    asm("mov.b64 {%0, %1}, %2;" : "=f"(lo), "=f"(hi) : "l"(v));
}
__device__ __forceinline__ void fma2(u64& d, u64 a, u64 b) {
    asm("fma.rn.f32x2 %0, %1, %2, %0;" : "+l"(d) : "l"(a), "l"(b));
}
__device__ __forceinline__ void mul2(u64& d, u64 a) {
    asm("mul.rn.f32x2 %0, %0, %1;" : "+l"(d) : "l"(a));
}

// ---------------- cp.async helpers --------------------------------------------
__device__ __forceinline__ void cp16(float* dst, const float* src) {
    unsigned s = (unsigned)__cvta_generic_to_shared(dst);
    asm volatile("cp.async.ca.shared.global [%0], [%1], 16;" :: "r"(s), "l"(src));
}
#define CP_COMMIT() asm volatile("cp.async.commit_group;")
#define CP_WAIT0()  asm volatile("cp.async.wait_group 0;")

// ---------------- micro tiles --------------------------------------------------
__device__ __forceinline__ void fma8x8(float4 a0, float4 a1,
                                       float4 b0, float4 b1, u64 (&c)[8][4]) {
    u64 p0 = pack2(b0.x, b0.y), p1 = pack2(b0.z, b0.w);
    u64 p2 = pack2(b1.x, b1.y), p3 = pack2(b1.z, b1.w);
    float as[8] = {a0.x, a0.y, a0.z, a0.w, a1.x, a1.y, a1.z, a1.w};
    #pragma unroll
    for (int ii = 0; ii < 8; ii++) {
        u64 ad = dup2(as[ii]);
        fma2(c[ii][0], ad, p0); fma2(c[ii][1], ad, p1);
        fma2(c[ii][2], ad, p2); fma2(c[ii][3], ad, p3);
    }
}
// 8 rows x 4 cols (QK in 512-thread flash)
__device__ __forceinline__ void fma8x4(float4 a0, float4 a1, float4 b,
                                       u64 (&c)[8][2]) {
    u64 p0 = pack2(b.x, b.y), p1 = pack2(b.z, b.w);
    float as[8] = {a0.x, a0.y, a0.z, a0.w, a1.x, a1.y, a1.z, a1.w};
    #pragma unroll
    for (int ii = 0; ii < 8; ii++) {
        u64 ad = dup2(as[ii]);
        fma2(c[ii][0], ad, p0); fma2(c[ii][1], ad, p1);
    }
}
// 8 rows x 2 cols (PV in 512-thread flash)
__device__ __forceinline__ void fma8x2(float4 a0, float4 a1, u64 bp, u64 (&c)[8]) {
    float as[8] = {a0.x, a0.y, a0.z, a0.w, a1.x, a1.y, a1.z, a1.w};
    #pragma unroll
    for (int ii = 0; ii < 8; ii++)
        fma2(c[ii], dup2(as[ii]), bp);
}

__device__ __forceinline__ void unpack_acc8(const u64 (&acc)[8][4], float (&s)[8][8]) {
    #pragma unroll
    for (int ii = 0; ii < 8; ii++)
        #pragma unroll
        for (int p = 0; p < 4; p++)
            unpack2(acc[ii][p], s[ii][2*p], s[ii][2*p+1]);
}

// ---------------- 128x128 sgemm core (BK=16, 256 thr, 8x8/thread) ------------
__device__ __forceinline__ void sgemm128(
    const float* __restrict__ A, int lda,
    const float* __restrict__ B, int ldb,
    int kdim, u64 (&acc)[8][4],
    float (*Ats)[128], float (*Bs)[128])
{
    const int tid = threadIdx.x;
    const int ty  = tid >> 4, tx = tid & 15;
    const int ar  = tid >> 1;
    const int ak  = (tid & 1) << 3;
    const int br0 = tid >> 5;
    const int bc  = (tid & 31) << 2;

    float4 a0 = *(const float4*)(A + (size_t)ar * lda + ak);
    float4 a1 = *(const float4*)(A + (size_t)ar * lda + ak + 4);
    float4 b0 = *(const float4*)(B + (size_t)br0 * ldb + bc);
    float4 b1 = *(const float4*)(B + (size_t)(br0 + 8) * ldb + bc);

    for (int k0 = 0; k0 < kdim; k0 += 16) {
        Ats[ak + 0][ar] = a0.x; Ats[ak + 1][ar] = a0.y;
        Ats[ak + 2][ar] = a0.z; Ats[ak + 3][ar] = a0.w;
        Ats[ak + 4][ar] = a1.x; Ats[ak + 5][ar] = a1.y;
        Ats[ak + 6][ar] = a1.z; Ats[ak + 7][ar] = a1.w;
        *(float4*)(&Bs[br0][bc])     = b0;
        *(float4*)(&Bs[br0 + 8][bc]) = b1;
        __syncthreads();
        if (k0 + 16 < kdim) {
            a0 = *(const float4*)(A + (size_t)ar * lda + k0 + 16 + ak);
            a1 = *(const float4*)(A + (size_t)ar * lda + k0 + 16 + ak + 4);
            b0 = *(const float4*)(B + (size_t)(k0 + 16 + br0) * ldb + bc);
            b1 = *(const float4*)(B + (size_t)(k0 + 24 + br0) * ldb + bc);
        }
        #pragma unroll
        for (int kk = 0; kk < 16; kk++) {
            float4 av0 = *(const float4*)(&Ats[kk][ty << 3]);
            float4 av1 = *(const float4*)(&Ats[kk][(ty << 3) + 4]);
            float4 bv0 = *(const float4*)(&Bs[kk][tx << 3]);
            float4 bv1 = *(const float4*)(&Bs[kk][(tx << 3) + 4]);
            fma8x8(av0, av1, bv0, bv1, acc);
        }
        __syncthreads();
    }
}

// ---------------- kernel 0: transpose+pad rel_emb ----------------------------
__global__ void __launch_bounds__(256) transpose_rel_kernel(
    const float* __restrict__ rel, float* __restrict__ relT)
{
    int idx = blockIdx.x * 256 + threadIdx.x;
    if (idx < DHEAD * RELTLD) {
        int d = idx / RELTLD;
        int t = idx % RELTLD;
        relT[idx] = (t < TVALS) ? rel[(size_t)t * DHEAD + d] : 0.0f;
    }
}

// ---------------- kernel 1: fused QKV projection (128x128 tiles) -------------
__global__ void __launch_bounds__(256, 2) gemm_qkv_kernel(
    const float* __restrict__ x,
    const float* __restrict__ Wq, const float* __restrict__ Wkv,
    float* __restrict__ Q, float* __restrict__ Qt,
    float* __restrict__ Kt, float* __restrict__ V)
{
    __shared__ float Ats[16][128];
    __shared__ float Bs[16][128];

    const int m0 = blockIdx.x << 7;
    const int c0 = blockIdx.y << 7;

    const float* W; int wcol, ldw;
    if (c0 < 512) { W = Wq;  wcol = c0;       ldw = 512;  }
    else          { W = Wkv; wcol = c0 - 512; ldw = 1024; }

    u64 acc[8][4] = {};
    sgemm128(x + (size_t)m0 * DIMM, DIMM, W + wcol, ldw, DIMM, acc, Ats, Bs);

    float s[8][8];
    unpack_acc8(acc, s);

    const int ty = threadIdx.x >> 4, tx = threadIdx.x & 15;
    const int colb = c0 + (tx << 3);

    if (c0 < 512) {
        #pragma unroll
        for (int ii = 0; ii < 8; ii++)
            #pragma unroll
            for (int jj = 0; jj < 8; jj++) s[ii][jj] *= SCALE_F;
        #pragma unroll
        for (int ii = 0; ii < 8; ii++) {
            int r = m0 + (ty << 3) + ii;
            int b = r >> 11, n = r & 2047;
            int head = (colb & 511) >> 6, dl = colb & 63;
            size_t base = (((size_t)(b * HEADS + head)) * NSEQ + n) * DHEAD + dl;
            *(float4*)(Q + base)     = make_float4(s[ii][0], s[ii][1], s[ii][2], s[ii][3]);
            *(float4*)(Q + base + 4) = make_float4(s[ii][4], s[ii][5], s[ii][6], s[ii][7]);
        }
        #pragma unroll
        for (int jj = 0; jj < 8; jj++) {
            int col = colb + jj;
            int head = (col & 511) >> 6, dl = col & 63;
            #pragma unroll
            for (int g = 0; g < 2; g++) {
                int r = m0 + (ty << 3) + g * 4;
                int b = r >> 11, n = r & 2047;
                size_t base = (size_t)(b * HEADS + head) * QT_BH + (size_t)dl * NSEQ + n;
                *(float4*)(Qt + base) = make_float4(s[g*4+0][jj], s[g*4+1][jj],
                                                    s[g*4+2][jj], s[g*4+3][jj]);
            }
        }
    } else if (c0 < 1024) {
        #pragma unroll
        for (int jj = 0; jj < 8; jj++) {
            int col = colb + jj;
            int head = (col & 511) >> 6, dl = col & 63;
            #pragma unroll
            for (int g = 0; g < 2; g++) {
                int r = m0 + (ty << 3) + g * 4;
                int b = r >> 11, n = r & 2047;
                size_t base = (size_t)(b * HEADS + head) * QT_BH + (size_t)dl * NSEQ + n;
                *(float4*)(Kt + base) = make_float4(s[g*4+0][jj], s[g*4+1][jj],
                                                    s[g*4+2][jj], s[g*4+3][jj]);
            }
        }
    } else {
        #pragma unroll
        for (int ii = 0; ii < 8; ii++) {
            int r = m0 + (ty << 3) + ii;
            int b = r >> 11, n = r & 2047;
            int head = (colb & 511) >> 6, dl = colb & 63;
            size_t base = (((size_t)(b * HEADS + head)) * NSEQ + n) * DHEAD + dl;
            *(float4*)(V + base)     = make_float4(s[ii][0], s[ii][1], s[ii][2], s[ii][3]);
            *(float4*)(V + base + 4) = make_float4(s[ii][4], s[ii][5], s[ii][6], s[ii][7]);
        }
    }
}

// ---------------- kernel 2: P = Qscaled @ relT  (32768 x 1025 x 64) ----------
__global__ void __launch_bounds__(256, 2) gemm_p_kernel(
    const float* __restrict__ Q, const float* __restrict__ relT,
    float* __restrict__ P)
{
    __shared__ float Ats[16][128];
    __shared__ float Bs[16][128];

    const int m0 = blockIdx.x << 7;
    const int t0 = blockIdx.y << 7;

    u64 acc[8][4] = {};
    sgemm128(Q + (size_t)m0 * DHEAD, DHEAD, relT + t0, RELTLD, DHEAD, acc, Ats, Bs);

    float s[8][8];
    unpack_acc8(acc, s);

    const int ty = threadIdx.x >> 4, tx = threadIdx.x & 15;
    const int colb = t0 + (tx << 3);
    const bool full = (t0 + 127) < TVALS;

    #pragma unroll
    for (int ii = 0; ii < 8; ii++) {
        size_t base = (size_t)(m0 + (ty << 3) + ii) * PLD + colb;
        if (full) {
            *(float4*)(P + base)     = make_float4(s[ii][0], s[ii][1], s[ii][2], s[ii][3]);
            *(float4*)(P + base + 4) = make_float4(s[ii][4], s[ii][5], s[ii][6], s[ii][7]);
        } else {
            #pragma unroll
            for (int jj = 0; jj < 8; jj++)
                if (colb + jj < TVALS) P[base + jj] = s[ii][jj];
        }
    }
}

// ---------------- kernel 3: flash attention, Br=Bc=128, 512 threads ----------
// grid (16, 16), 512 threads (16 warps), 224 KB dyn smem, 1 CTA/SM.
// Per-thread: QK 8x4 (s2[8][2]), PV 8x2 (o2[8]); regs capped at 128.
__global__ void __launch_bounds__(512, 1) flash_kernel(
    const float* __restrict__ Qt, const float* __restrict__ Kt,
    const float* __restrict__ V, const float* __restrict__ P,
    float* __restrict__ O)
{
    extern __shared__ float smf[];
    float* Qts  = smf;                   // [64][128]
    float* Ktb0 = smf + 8192;            // [64][128] double-buffered
    float* Ktb1 = smf + 16384;
    float* Vb0  = smf + 24576;           // [128][64] double-buffered
    float* Vb1  = smf + 32768;
    float* Pts  = smf + 40960;           // [128][128] swizzled

    const int bh = blockIdx.y;
    const int n0 = blockIdx.x << 7;
    const float* Qb = Qt + (size_t)bh * QT_BH;
    const float* Kb = Kt + (size_t)bh * QT_BH;
    const float* Vg = V  + (size_t)bh * NSEQ * DHEAD;
    const float* Pb = P  + (size_t)bh * NSEQ * PLD;

    const int tid = threadIdx.x;
    const int ty  = tid >> 5;            // 0..15 -> rows ty*8..+7
    const int tx  = tid & 31;            // 0..31 -> QK cols tx*4..+3, PV cols tx*2..+1

    // staging coords: K/Q tiles are 2048 float4 -> 4 per thread
    // stage Q (plain stores; visible after first barrier)
    #pragma unroll
    for (int q = 0; q < 4; q++) {
        int idx = (q << 9) + tid;
        int d = idx >> 5, c = (idx & 31) << 2;
        *(float4*)(Qts + d * 128 + c) =
            *(const float4*)(Qb + (size_t)d * NSEQ + n0 + c);
    }

    // prologue: cp.async tile 0
    #pragma unroll
    for (int q = 0; q < 4; q++) {
        int idx = (q << 9) + tid;
        int d = idx >> 5, c = (idx & 31) << 2;
        cp16(Ktb0 + d * 128 + c, Kb + (size_t)d * NSEQ + c);
    }
    #pragma unroll
    for (int q = 0; q < 4; q++) {
        int idx = (q << 9) + tid;
        int row = idx >> 4, c = (idx & 15) << 2;
        cp16(Vb0 + row * 64 + c, Vg + (size_t)row * DHEAD + c);
    }
    CP_COMMIT();

    float m_i[8], l_i[8];
    u64 o2[8];
    #pragma unroll
    for (int ii = 0; ii < 8; ii++) {
        m_i[ii] = -1e30f; l_i[ii] = 0.0f; o2[ii] = 0ull;
    }

    int cur = 0;
    for (int jt = 0; jt < NSEQ / 128; jt++) {
        const int j0 = jt << 7;
        const float* Kc = cur ? Ktb1 : Ktb0;
        const float* Vc = cur ? Vb1  : Vb0;

        CP_WAIT0();
        __syncthreads();                                   // A

        // ---- S = Q K^T (8x4 per thread) --------------------------------------
        u64 s2[8][2] = {};
        #pragma unroll 4
        for (int d = 0; d < 64; d++) {
            float4 av0 = *(const float4*)(Qts + d * 128 + (ty << 3));
            float4 av1 = *(const float4*)(Qts + d * 128 + (ty << 3) + 4);
            float4 bv  = *(const float4*)(Kc  + d * 128 + (tx << 2));
            fma8x4(av0, av1, bv, s2);
        }

        // ---- bias + online softmax -------------------------------------------
        float s[8][4];
        float rowmax[8];
        #pragma unroll
        for (int ii = 0; ii < 8; ii++) {
            unpack2(s2[ii][0], s[ii][0], s[ii][1]);
            unpack2(s2[ii][1], s[ii][2], s[ii][3]);
            int n = n0 + (ty << 3) + ii;
            const float* prow = Pb + (size_t)n * PLD;
            int basei = n - j0 + 512 - (tx << 2);
            rowmax[ii] = -1e30f;
            #pragma unroll
            for (int jj = 0; jj < 4; jj++) {
                int idx = basei - jj;
                idx = idx < 0 ? 0 : (idx > 1024 ? 1024 : idx);
                float v = s[ii][jj] + prow[idx];
                s[ii][jj] = v;
                rowmax[ii] = fmaxf(rowmax[ii], v);
            }
        }
        #pragma unroll
        for (int msk = 1; msk < 32; msk <<= 1)
            #pragma unroll
            for (int ii = 0; ii < 8; ii++)
                rowmax[ii] = fmaxf(rowmax[ii],
                                   __shfl_xor_sync(0xffffffffu, rowmax[ii], msk));

        float rs[8];
        #pragma unroll
        for (int ii = 0; ii < 8; ii++) {
            float mnew = fmaxf(m_i[ii], rowmax[ii]);
            float corr = __expf(m_i[ii] - mnew);
            m_i[ii] = mnew;
            rs[ii] = 0.0f;
            #pragma unroll
            for (int jj = 0; jj < 4; jj++) {
                float p = __expf(s[ii][jj] - mnew);
                s[ii][jj] = p;
                rs[ii] += p;
            }
            l_i[ii] *= corr;
            mul2(o2[ii], dup2(corr));
        }
        #pragma unroll
        for (int msk = 1; msk < 32; msk <<= 1)
            #pragma unroll
            for (int ii = 0; ii < 8; ii++)
                rs[ii] += __shfl_xor_sync(0xffffffffu, rs[ii], msk);
        #pragma unroll
        for (int ii = 0; ii < 8; ii++) l_i[ii] += rs[ii];

        // ---- stage S transposed into Pts (swizzled i-quads) -------------------
        // write: j = tx*4+jj; i-quad q stored at (q ^ ((j>>2)&7)) * 4
        {
            int sw = tx & 7;  // == (j>>2)&7 for j = tx*4+jj, jj<4
            #pragma unroll
            for (int jj = 0; jj < 4; jj++) {
                int j = (tx << 2) + jj;
                *(float4*)(Pts + j * 128 + ((((ty << 1))     ^ sw) << 2)) =
                    make_float4(s[0][jj], s[1][jj], s[2][jj], s[3][jj]);
                *(float4*)(Pts + j * 128 + ((((ty << 1) | 1) ^ sw) << 2)) =
                    make_float4(s[4][jj], s[5][jj], s[6][jj], s[7][jj]);
            }
        }
        __syncthreads();                                   // B

        // ---- issue cp.async for next tile (overlaps PV) -----------------------
        if (jt + 1 < NSEQ / 128) {
            float* Kn = cur ? Ktb0 : Ktb1;
            float* Vn = cur ? Vb0  : Vb1;
            const int jn = j0 + 128;
            #pragma unroll
            for (int q = 0; q < 4; q++) {
                int idx = (q << 9) + tid;
                int d = idx >> 5, c = (idx & 31) << 2;
                cp16(Kn + d * 128 + c, Kb + (size_t)d * NSEQ + jn + c);
            }
            #pragma unroll
            for (int q = 0; q < 4; q++) {
                int idx = (q << 9) + tid;
                int row = idx >> 4, c = (idx & 15) << 2;
                cp16(Vn + row * 64 + c, Vg + (size_t)(jn + row) * DHEAD + c);
            }
            CP_COMMIT();
        }

        // ---- O += P V (8x2 per thread) ----------------------------------------
        #pragma unroll 4
        for (int j = 0; j < 128; j++) {
            int sw = (j >> 2) & 7;
            float4 a0 = *(const float4*)(Pts + j * 128 + ((((ty << 1))     ^ sw) << 2));
            float4 a1 = *(const float4*)(Pts + j * 128 + ((((ty << 1) | 1) ^ sw) << 2));
            float2 bv = *(const float2*)(Vc + j * 64 + (tx << 1));
            fma8x2(a0, a1, pack2(bv.x, bv.y), o2);
        }
        cur ^= 1;
    }

    // epilogue: normalize, write [b][n][h*64+dd]
    const int b = bh >> 3, head = bh & 7;
    #pragma unroll
    for (int ii = 0; ii < 8; ii++) {
        int n = n0 + (ty << 3) + ii;
        float inv = 1.0f / l_i[ii];
        float2 v;
        unpack2(o2[ii], v.x, v.y);
        v.x *= inv; v.y *= inv;
        size_t base = ((size_t)(b * NSEQ + n)) * DIMM + (head << 6) + (tx << 1);
        *(float2*)(O + base) = v;
    }
}

// ---------------- kernel 4: output projection + bias (128x128) ----------------
__global__ void __launch_bounds__(256, 2) gemm_out_kernel(
    const float* __restrict__ O, const float* __restrict__ Wo,
    const float* __restrict__ bo, float* __restrict__ out)
{
    __shared__ float Ats[16][128];
    __shared__ float Bs[16][128];

    const int m0 = blockIdx.x << 7;
    const int n0 = blockIdx.y << 7;

    u64 acc[8][4] = {};
    sgemm128(O + (size_t)m0 * DIMM, DIMM, Wo + n0, DIMM, DIMM, acc, Ats, Bs);

    float s[8][8];
    unpack_acc8(acc, s);

    const int ty = threadIdx.x >> 4, tx = threadIdx.x & 15;
    const int col = n0 + (tx << 3);
    float4 bias0 = *(const float4*)(bo + col);
    float4 bias1 = *(const float4*)(bo + col + 4);
    #pragma unroll
    for (int ii = 0; ii < 8; ii++) {
        size_t base = (size_t)(m0 + (ty << 3) + ii) * DIMM + col;
        *(float4*)(out + base)     = make_float4(s[ii][0] + bias0.x, s[ii][1] + bias0.y,
                                                 s[ii][2] + bias0.z, s[ii][3] + bias0.w);
        *(float4*)(out + base + 4) = make_float4(s[ii][4] + bias1.x, s[ii][5] + bias1.y,
                                                 s[ii][6] + bias1.z, s[ii][7] + bias1.w);
    }
}

// ---------------- launch -------------------------------------------------------
extern "C" void kernel_launch(void* const* d_in, const int* in_sizes, int n_in,
                              void* d_out, int out_size)
{
    const float* x    = (const float*)d_in[0];
    const float* Wq   = (const float*)d_in[1];
    const float* Wkv  = (const float*)d_in[2];
    const float* Wo   = (const float*)d_in[3];
    const float* bo   = (const float*)d_in[4];
    const float* rel  = (const float*)d_in[5];
    float* out = (float*)d_out;

    float *Qp, *Qtp, *Ktp, *Vp, *Pp, *Op, *rTp;
    cudaGetSymbolAddress((void**)&Qp,  g_Q);
    cudaGetSymbolAddress((void**)&Qtp, g_Qt);
    cudaGetSymbolAddress((void**)&Ktp, g_Kt);
    cudaGetSymbolAddress((void**)&Vp,  g_V);
    cudaGetSymbolAddress((void**)&Pp,  g_P);
    cudaGetSymbolAddress((void**)&Op,  g_O);
    cudaGetSymbolAddress((void**)&rTp, g_relT);

    cudaFuncSetAttribute(flash_kernel,
                         cudaFuncAttributeMaxDynamicSharedMemorySize, 229376);

    transpose_rel_kernel<<<(DHEAD * RELTLD + 255) / 256, 256>>>(rel, rTp);
    gemm_qkv_kernel<<<dim3(MROWS / 128, 12), 256>>>(x, Wq, Wkv, Qp, Qtp, Ktp, Vp);
    gemm_p_kernel<<<dim3(QROWS / 128, 9), 256>>>(Qp, rTp, Pp);
    flash_kernel<<<dim3(NSEQ / 128, BHDIM), 512, 229376>>>(Qtp, Ktp, Vp, Pp, Op);
    gemm_out_kernel<<<dim3(MROWS / 128, DIMM / 128), 256>>>(Op, Wo, bo, out);
}